// round 8
// baseline (speedup 1.0000x reference)
#include <cuda_runtime.h>
#include <cuda_fp16.h>

#define TEXN   1024
#define TT     (TEXN * TEXN)
#define CH     16
#define BB     4
#define HH     768
#define WW     768
#define HW     (HH * WW)
#define NPIX   (BB * HW)

#define CLAMP_LO (-123.68f)
#define CLAMP_HI (151.061f)

// Channel-interleaved clamped texture, fp16 [y][x][c] (33.5 MB, L2-resident).
// +32 halves zero pad: 64B span load at x0==1023 overreads 32B; wx==0 there
// so the zero pad contributes 0*0 (no NaN).
__device__ __half g_tex[TT * CH + 32];

// ---------------------------------------------------------------------------
// Pass 1: clamp + transpose + fp16 convert, [C,T,T] f32 -> [T,T,C] f16.
// ---------------------------------------------------------------------------
__global__ __launch_bounds__(256)
void clamp_transpose_kernel(const float* __restrict__ data) {
    int p4 = (blockIdx.x * blockDim.x + threadIdx.x) * 4;
    if (p4 >= TT) return;

    __half h[4][CH];
#pragma unroll
    for (int c = 0; c < CH; c++) {
        float4 t = __ldcs(reinterpret_cast<const float4*>(&data[c * TT + p4]));
        h[0][c] = __float2half_rn(fminf(fmaxf(t.x, CLAMP_LO), CLAMP_HI));
        h[1][c] = __float2half_rn(fminf(fmaxf(t.y, CLAMP_LO), CLAMP_HI));
        h[2][c] = __float2half_rn(fminf(fmaxf(t.z, CLAMP_LO), CLAMP_HI));
        h[3][c] = __float2half_rn(fminf(fmaxf(t.w, CLAMP_LO), CLAMP_HI));
    }

    uint4* dst = reinterpret_cast<uint4*>(g_tex + (size_t)p4 * CH);
#pragma unroll
    for (int i = 0; i < 4; i++) {
        const uint4* src = reinterpret_cast<const uint4*>(&h[i][0]);
        dst[i * 2 + 0] = src[0];
        dst[i * 2 + 1] = src[1];
    }
}

// ---------------------------------------------------------------------------
// Pass 2: bilinear sample. 4 threads/pixel, 4 PIXELS PER THREAD,
// 256 px/block (256 threads). All 8 texture LDG.128 + 4 grid loads issued
// before any dependent compute -> MLP=8 per thread; SM-wide outstanding
// loads preserved at halved occupancy, per-pixel overheads halved.
//   Loads:   lane q takes the q-th 16B of the 64B (x0,x1) row span.
//   Exchange: 2 SHFL.32 per row -> other x-corner for my own 4 channels.
//   Math:    x-lerp half2, y-lerp fp32.
//   Stores:  smem [16][260], XOR-swizzled cols (conflict-free STS/LDS),
//            writeback 1KB-contiguous float4 __stcs per channel plane.
// ---------------------------------------------------------------------------
#define NPX_T   4                 // pixels per thread
#define PXB     256               // pixels per block
#define SOUT_STRIDE 260           // 256 + 4 pad floats; 1040B row, 16B aligned

struct PixIn {
    uint4 u0, u1;                 // raw 16B quarters, rows y0/y1
    float wx, wy;
};

__device__ __forceinline__ void load_pix(float2 g, const char* tbase,
                                         unsigned qoff, PixIn& p) {
    float ix = fminf(fmaxf(fmaf(g.x, 511.5f, 511.5f), 0.0f), 1023.0f);
    float iy = fminf(fmaxf(fmaf(g.y, 511.5f, 511.5f), 0.0f), 1023.0f);
    float x0f = floorf(ix), y0f = floorf(iy);
    p.wx = ix - x0f; p.wy = iy - y0f;
    int x0 = (int)x0f, y0 = (int)y0f;
    unsigned r0 = ((unsigned)y0 << 15) + ((unsigned)x0 << 5) + qoff;
    unsigned r1 = r0 + ((y0 < TEXN - 1) ? 32768u : 0u);
    p.u0 = *reinterpret_cast<const uint4*>(tbase + r0);
    p.u1 = *reinterpret_cast<const uint4*>(tbase + r1);
}

__device__ __forceinline__ void compute_pix(const PixIn& p, bool hiX, float* res) {
    unsigned recv0a = __shfl_xor_sync(0xffffffffu, hiX ? p.u0.x : p.u0.z, 2);
    unsigned recv0b = __shfl_xor_sync(0xffffffffu, hiX ? p.u0.y : p.u0.w, 2);
    unsigned recv1a = __shfl_xor_sync(0xffffffffu, hiX ? p.u1.x : p.u1.z, 2);
    unsigned recv1b = __shfl_xor_sync(0xffffffffu, hiX ? p.u1.y : p.u1.w, 2);

    unsigned own0a = hiX ? p.u0.z : p.u0.x;
    unsigned own0b = hiX ? p.u0.w : p.u0.y;
    unsigned own1a = hiX ? p.u1.z : p.u1.x;
    unsigned own1b = hiX ? p.u1.w : p.u1.y;

    float w_own = hiX ? p.wx : (1.0f - p.wx);
    __half2 wo2 = __float2half2_rn(w_own);
    __half2 wt2 = __float2half2_rn(1.0f - w_own);

    __half2 r0a = __hfma2(*reinterpret_cast<const __half2*>(&recv0a), wt2,
                  __hmul2(*reinterpret_cast<const __half2*>(&own0a), wo2));
    __half2 r0b = __hfma2(*reinterpret_cast<const __half2*>(&recv0b), wt2,
                  __hmul2(*reinterpret_cast<const __half2*>(&own0b), wo2));
    __half2 r1a = __hfma2(*reinterpret_cast<const __half2*>(&recv1a), wt2,
                  __hmul2(*reinterpret_cast<const __half2*>(&own1a), wo2));
    __half2 r1b = __hfma2(*reinterpret_cast<const __half2*>(&recv1b), wt2,
                  __hmul2(*reinterpret_cast<const __half2*>(&own1b), wo2));

    float2 f0a = __half22float2(r0a);
    float2 f0b = __half22float2(r0b);
    float2 f1a = __half22float2(r1a);
    float2 f1b = __half22float2(r1b);

    res[0] = f0a.x + (f1a.x - f0a.x) * p.wy;
    res[1] = f0a.y + (f1a.y - f0a.y) * p.wy;
    res[2] = f0b.x + (f1b.x - f0b.x) * p.wy;
    res[3] = f0b.y + (f1b.y - f0b.y) * p.wy;
}

__global__ __launch_bounds__(256)
void sample_kernel(const float2* __restrict__ grid, float* __restrict__ out) {
    __shared__ __align__(16) float s_out[CH * SOUT_STRIDE];

    int tid = threadIdx.x;
    int lp  = tid >> 2;                  // 0..63; handles px lp + 64*i
    int q   = tid & 3;
    int base = blockIdx.x * PXB;         // exact grid; HW % 256 == 0

    const char* tbase = reinterpret_cast<const char*>(g_tex);
    unsigned qoff = (unsigned)q << 4;

    // ---- issue all independent loads up front ----
    float2 g[NPX_T];
#pragma unroll
    for (int i = 0; i < NPX_T; i++)
        g[i] = __ldg(&grid[base + lp + 64 * i]);

    PixIn p[NPX_T];
#pragma unroll
    for (int i = 0; i < NPX_T; i++)
        load_pix(g[i], tbase, qoff, p[i]);

    bool hiX = (q & 2) != 0;
    int ch   = (q & 1) * 8 + (q & 2) * 2;         // 0-3,8-11,4-7,12-15
    int col0 = lp ^ ((q & 1) << 3);               // XOR swizzle in low 6 bits

#pragma unroll
    for (int i = 0; i < NPX_T; i++) {
        float res[4];
        compute_pix(p[i], hiX, res);
#pragma unroll
        for (int j = 0; j < 4; j++)
            s_out[(ch + j) * SOUT_STRIDE + col0 + 64 * i] = res[j];
    }

    __syncthreads();

    // Writeback: 4 rounds; round r, idx = tid + 256r -> channel idx>>6,
    // float4 group v = idx&63. Un-swizzle group: v ^ 2*k(c).
    int b  = base / HW;
    int hw = base - b * HW;              // multiple of 256
#pragma unroll
    for (int r = 0; r < NPX_T; r++) {
        int idx = tid + r * 256;
        int c = idx >> 6;                // 0..15, constant per warp
        int v = idx & 63;
        int vv = v ^ (((c >> 3) & 1) << 1);
        float4 val = *reinterpret_cast<const float4*>(&s_out[c * SOUT_STRIDE + vv * 4]);
        float* o = out + ((size_t)b * CH + c) * HW + hw + v * 4;
        __stcs(reinterpret_cast<float4*>(o), val);
    }
}

extern "C" void kernel_launch(void* const* d_in, const int* in_sizes, int n_in,
                              void* d_out, int out_size) {
    const float* x_grid = (const float*)d_in[0];
    const float* data   = (const float*)d_in[1];
    if (n_in >= 2 && in_sizes[0] == TT * CH) {
        data   = (const float*)d_in[0];
        x_grid = (const float*)d_in[1];
    }

    float* out = (float*)d_out;

    {
        int threads = 256;
        int blocks = (TT / 4 + threads - 1) / threads;  // 1024
        clamp_transpose_kernel<<<blocks, threads>>>(data);
    }
    {
        int blocks = NPIX / PXB;                         // 9216, exact
        sample_kernel<<<blocks, 256>>>((const float2*)x_grid, out);
    }
}